// round 1
// baseline (speedup 1.0000x reference)
#include <cuda_runtime.h>
#include <cuda_bf16.h>

// Levinson-Durbin, M=24, one row per thread.
// out[row] = [K, a0..a23] where R a = -r1, K = sqrt(r0 + r1.a) = sqrt(E_M).
//
// Memory strategy: rows are 25 floats (100 B, not 16B-aligned), so we stage
// a block's worth (256 rows = 6400 floats = 1600 float4) through shared
// memory with fully coalesced float4 traffic, and read/write per-row data
// from smem at stride 25 (odd -> bank-conflict-free).

constexpr int M_ORD = 24;
constexpr int NC    = M_ORD + 1;   // 25
constexpr int TPB   = 256;
constexpr int NV4   = TPB * NC / 4; // 1600 float4 per block

__global__ __launch_bounds__(TPB)
void levinson_durbin_kernel(const float* __restrict__ r,
                            float* __restrict__ out,
                            int nrows)
{
    __shared__ float sbuf[TPB * NC];   // 25600 B
    const int tid  = threadIdx.x;
    const int row0 = blockIdx.x * TPB;
    const bool full_block = (row0 + TPB) <= nrows;

    float rr[NC];

    if (full_block) {
        // Coalesced vector load: gmem -> smem
        const float4* gin = reinterpret_cast<const float4*>(r + (size_t)row0 * NC);
        float4* s4 = reinterpret_cast<float4*>(sbuf);
        #pragma unroll
        for (int i = tid; i < NV4; i += TPB) s4[i] = gin[i];
        __syncthreads();
        #pragma unroll
        for (int i = 0; i < NC; i++) rr[i] = sbuf[tid * NC + i];
        __syncthreads();   // before sbuf is reused for output
    } else {
        // Tail path (not hit for BATCH=262144, kept for safety)
        int row = row0 + tid;
        if (row < nrows) {
            #pragma unroll
            for (int i = 0; i < NC; i++) rr[i] = r[(size_t)row * NC + i];
        } else {
            #pragma unroll
            for (int i = 0; i < NC; i++) rr[i] = (i == 0) ? 1.0f : 0.0f;
        }
    }

    // ---- Levinson-Durbin recursion (fully unrolled, M=24) ----
    float a[M_ORD];
    float E = rr[0];
    #pragma unroll
    for (int m = 0; m < M_ORD; m++) {
        float acc = rr[m + 1];
        #pragma unroll
        for (int i = 0; i < m; i++)
            acc = fmaf(a[i], rr[m - i], acc);
        float k = __fdividef(-acc, E);
        // symmetric in-place update: a_i' = a_i + k * a_{m-1-i}
        #pragma unroll
        for (int i = 0; i < m / 2; i++) {
            float t = a[i];
            float u = a[m - 1 - i];
            a[i]         = fmaf(k, u, t);
            a[m - 1 - i] = fmaf(k, t, u);
        }
        if (m & 1) {
            float t = a[m / 2];
            a[m / 2] = fmaf(k, t, t);
        }
        a[m] = k;
        E = fmaf(-k * k, E, E);     // E *= (1 - k^2)
    }
    const float Kv = sqrtf(E);

    if (full_block) {
        // Stage results in smem, then coalesced vector store
        sbuf[tid * NC + 0] = Kv;
        #pragma unroll
        for (int i = 0; i < M_ORD; i++) sbuf[tid * NC + 1 + i] = a[i];
        __syncthreads();
        float4* gout = reinterpret_cast<float4*>(out + (size_t)row0 * NC);
        const float4* s4 = reinterpret_cast<const float4*>(sbuf);
        #pragma unroll
        for (int i = tid; i < NV4; i += TPB) gout[i] = s4[i];
    } else {
        int row = row0 + tid;
        if (row < nrows) {
            out[(size_t)row * NC + 0] = Kv;
            #pragma unroll
            for (int i = 0; i < M_ORD; i++)
                out[(size_t)row * NC + 1 + i] = a[i];
        }
    }
}

extern "C" void kernel_launch(void* const* d_in, const int* in_sizes, int n_in,
                              void* d_out, int out_size)
{
    const float* r = (const float*)d_in[0];
    float* out = (float*)d_out;
    const int nrows = in_sizes[0] / NC;
    const int grid = (nrows + TPB - 1) / TPB;
    levinson_durbin_kernel<<<grid, TPB>>>(r, out, nrows);
}